// round 1
// baseline (speedup 1.0000x reference)
#include <cuda_runtime.h>

#define S 64
#define D 524288            // 512*32*32
#define DQ (D / 4)          // 131072 float4 columns per row
#define P1_BLOCKS 128
#define P1_THREADS 256
#define CHUNK (DQ / P1_BLOCKS)      // 1024 float4 per block
#define COLS_PER_LANE (CHUNK / 32)  // 32
#define P2_BLOCKS 256
#define P2_THREADS 256

// scratch (no device allocations allowed)
__device__ float g_part[P1_BLOCKS * 128];   // per-block: [64 N partials][64 A partials]
__device__ float g_coeff[3 * S];            // [cp(64)][cc(64)][cn(64)]

__device__ __forceinline__ float dot4(float4 a, float4 b) {
    return a.x * b.x + a.y * b.y + a.z * b.z + a.w * b.w;
}

// Pass 1: warp w of each block owns s-range [8w, 8w+8); computes partial
// n[s] = q_s . q_s  and  a[s] = q_s . q_{s+1} over the block's column chunk.
__global__ __launch_bounds__(P1_THREADS) void dots_kernel(const float4* __restrict__ q4) {
    const int w    = threadIdx.x >> 5;
    const int lane = threadIdx.x & 31;
    const int s0   = w * 8;
    const int base = blockIdx.x * CHUNK;

    float accN[8], accA[8];
#pragma unroll
    for (int r = 0; r < 8; r++) { accN[r] = 0.f; accA[r] = 0.f; }

    for (int i = 0; i < COLS_PER_LANE; i++) {
        const int col = base + lane + (i << 5);
        float4 cur = q4[(size_t)s0 * DQ + col];
        accN[0] += dot4(cur, cur);
#pragma unroll
        for (int r = 1; r < 8; r++) {
            float4 nx = q4[(size_t)(s0 + r) * DQ + col];
            accN[r]     += dot4(nx, nx);
            accA[r - 1] += dot4(cur, nx);
            cur = nx;
        }
        if (s0 + 8 < S) {  // last warp has no a[63]
            float4 nx = q4[(size_t)(s0 + 8) * DQ + col];
            accA[7] += dot4(cur, nx);
        }
    }

    // warp-reduce the 16 accumulators
#pragma unroll
    for (int r = 0; r < 8; r++) {
#pragma unroll
        for (int off = 16; off > 0; off >>= 1) {
            accN[r] += __shfl_xor_sync(0xFFFFFFFFu, accN[r], off);
            accA[r] += __shfl_xor_sync(0xFFFFFFFFu, accA[r], off);
        }
    }

    if (lane == 0) {
        float* pb = g_part + blockIdx.x * 128;
#pragma unroll
        for (int r = 0; r < 8; r++) {
            pb[s0 + r]      = accN[r];
            pb[64 + s0 + r] = accA[r];   // slot 64+63 is written 0, never read
        }
    }
}

// Pass 2 (tiny): deterministic reduction over block partials, entropy branch
// ladder, softmax of 2, emit per-slice coefficients (cp, cc, cn).
__global__ void coeff_kernel(const float* __restrict__ ent) {
    __shared__ float shN[S], shA[S];
    const int s = threadIdx.x;
    if (s < S) {
        float sN = 0.f, sA = 0.f;
        for (int b = 0; b < P1_BLOCKS; b++) {
            sN += g_part[b * 128 + s];
            sA += g_part[b * 128 + 64 + s];
        }
        shN[s] = sN;
        shA[s] = sA;
    }
    __syncthreads();
    if (s >= S) return;

    int k1, k2;
    if (s == 0) {
        const int b0 = (ent[0] >= ent[1]) ? 1 : 0;
        k1 = b0; k2 = b0;
    } else if (s == S - 1) {
        const int bL = (ent[S - 1] >= ent[S - 2]) ? (S - 2) : (S - 1);
        k1 = bL; k2 = bL;
    } else {
        const float e  = ent[s];
        const float ep = ent[s - 1];
        const float en = ent[s + 1];
        const bool ge_next = e >= en, ge_prev = e >= ep;
        const bool le_next = e <= en, le_prev = e <= ep;
        if (ge_next && ge_prev)      { k1 = s - 1; k2 = s + 1; }
        else if (le_next && ge_prev) { k1 = s - 1; k2 = s;     }
        else if (ge_next && le_prev) { k1 = s;     k2 = s + 1; }
        else                         { k1 = s;     k2 = s;     }
    }

    const float d1 = (k1 == s) ? shN[s] : ((k1 == s - 1) ? shA[s - 1] : shA[s]);
    const float d2 = (k2 == s) ? shN[s] : ((k2 == s - 1) ? shA[s - 1] : shA[s]);

    const float scale = rsqrtf((float)D);
    const float s1 = d1 * scale, s2 = d2 * scale;
    const float m  = fmaxf(s1, s2);
    float w1 = expf(s1 - m), w2 = expf(s2 - m);
    const float inv = 1.f / (w1 + w2);
    w1 *= inv; w2 *= inv;

    float cp = 0.f, cc = 0.f, cn = 0.f;
    if (k1 == s - 1) cp += w1; else if (k1 == s) cc += w1; else cn += w1;
    if (k2 == s - 1) cp += w2; else if (k2 == s) cc += w2; else cn += w2;

    g_coeff[s]           = cp;
    g_coeff[64 + s]      = cc;
    g_coeff[128 + s]     = cn;
}

// Pass 3: out[s] = cp[s]*q[s-1] + cc[s]*q[s] + cn[s]*q[s+1].
// Rolling 3-row register window per float4 column; 2 independent column chains
// per thread for MLP. cp[0] == 0 and cn[63] == 0 by construction, so clamped
// boundary reads are multiplied by zero.
__global__ __launch_bounds__(P2_THREADS) void out_kernel(const float4* __restrict__ q4,
                                                         float4* __restrict__ o4) {
    __shared__ float scp[S], scc[S], scn[S];
    const int t = threadIdx.x;
    if (t < S) {
        scp[t] = g_coeff[t];
        scc[t] = g_coeff[64 + t];
        scn[t] = g_coeff[128 + t];
    }
    __syncthreads();

    const int j0 = blockIdx.x * P2_THREADS + t;
    const int j1 = j0 + DQ / 2;

    float4 b0 = q4[j0],       b1 = q4[j1];
    float4 c0 = q4[DQ + j0],  c1 = q4[DQ + j1];
    float4 a0 = b0,           a1 = b1;

#pragma unroll 4
    for (int s = 0; s < S; s++) {
        float4 d0, d1;
        if (s + 2 < S) {
            d0 = q4[(size_t)(s + 2) * DQ + j0];
            d1 = q4[(size_t)(s + 2) * DQ + j1];
        } else {
            d0 = c0; d1 = c1;
        }
        const float cp = scp[s], cc = scc[s], cn = scn[s];

        float4 o0, o1;
        o0.x = cp * a0.x + cc * b0.x + cn * c0.x;
        o0.y = cp * a0.y + cc * b0.y + cn * c0.y;
        o0.z = cp * a0.z + cc * b0.z + cn * c0.z;
        o0.w = cp * a0.w + cc * b0.w + cn * c0.w;
        o1.x = cp * a1.x + cc * b1.x + cn * c1.x;
        o1.y = cp * a1.y + cc * b1.y + cn * c1.y;
        o1.z = cp * a1.z + cc * b1.z + cn * c1.z;
        o1.w = cp * a1.w + cc * b1.w + cn * c1.w;

        o4[(size_t)s * DQ + j0] = o0;
        o4[(size_t)s * DQ + j1] = o1;

        a0 = b0; b0 = c0; c0 = d0;
        a1 = b1; b1 = c1; c1 = d1;
    }
}

extern "C" void kernel_launch(void* const* d_in, const int* in_sizes, int n_in,
                              void* d_out, int out_size) {
    const float4* q4  = (const float4*)d_in[0];
    const float*  ent = (const float*)d_in[1];
    float4*       o4  = (float4*)d_out;

    dots_kernel<<<P1_BLOCKS, P1_THREADS>>>(q4);
    coeff_kernel<<<1, S>>>(ent);
    out_kernel<<<P2_BLOCKS, P2_THREADS>>>(q4, o4);
}

// round 2
// speedup vs baseline: 1.2853x; 1.2853x over previous
#include <cuda_runtime.h>

#define S 64
#define D 524288            // 512*32*32
#define DQ (D / 4)          // 131072 float4 columns per row

// ---- pass 1 tiling ----
#define P1_THREADS 256
#define P1_CCHUNKS 512      // DQ / P1_THREADS
#define P1_SGROUPS 8        // 8 rows (+1 halo) per group

// ---- pass 3 tiling ----
#define P3_THREADS 256
#define P3_COLS    512      // float4 cols per block (2 chains/thread)
#define P3_CCHUNKS (DQ / P3_COLS)   // 256
#define P3_STILE   16
#define P3_SGROUPS (S / P3_STILE)   // 4

// scratch (no device allocations allowed)
// g_part[p * 512 + cx]; p = k*8+sg, k<8 -> N[sg*8+k], k>=8 -> A[sg*8+k-8]
__device__ float g_part[128 * P1_CCHUNKS];
__device__ float g_coeff[3 * S];            // [cp(64)][cc(64)][cn(64)]

__device__ __forceinline__ float dot4(float4 a, float4 b) {
    return a.x * b.x + a.y * b.y + a.z * b.z + a.w * b.w;
}

// Pass 1: block = (col chunk cx, s-group sg). Each thread owns one float4
// column, loads 9 rows front-batched (MLP=9), computes 8 N + 8 A partials.
__global__ __launch_bounds__(P1_THREADS) void dots_kernel(const float4* __restrict__ q4) {
    const int sg  = blockIdx.y;
    const int s0  = sg * 8;
    const int col = blockIdx.x * P1_THREADS + threadIdx.x;
    const int w    = threadIdx.x >> 5;
    const int lane = threadIdx.x & 31;

    float4 r[9];
#pragma unroll
    for (int k = 0; k < 9; k++) {
        int row = s0 + k;
        if (row > S - 1) row = S - 1;   // sg==7 halo; its A[63] is never read
        r[k] = q4[(size_t)row * DQ + col];
    }

    float v[16];
#pragma unroll
    for (int k = 0; k < 8; k++) {
        v[k]     = dot4(r[k], r[k]);        // N[s0+k]
        v[k + 8] = dot4(r[k], r[k + 1]);    // A[s0+k]
    }

    // warp shuffle reduce all 16 values
#pragma unroll
    for (int k = 0; k < 16; k++) {
#pragma unroll
        for (int off = 16; off > 0; off >>= 1)
            v[k] += __shfl_xor_sync(0xFFFFFFFFu, v[k], off);
    }

    __shared__ float sh[16][8];
    if (lane == 0) {
#pragma unroll
        for (int k = 0; k < 16; k++) sh[k][w] = v[k];
    }
    __syncthreads();

    if (threadIdx.x < 16) {
        float sum = 0.f;
#pragma unroll
        for (int j = 0; j < 8; j++) sum += sh[threadIdx.x][j];
        // transposed store: reduction in pass 2 reads contiguous 512 floats
        g_part[(threadIdx.x * 8 + sg) * P1_CCHUNKS + blockIdx.x] = sum;
    }
}

// Pass 2 (tiny): coalesced warp-per-target reduction of the 512 partials,
// then entropy branch ladder + softmax-of-2 -> per-slice (cp, cc, cn).
__global__ void coeff_kernel(const float* __restrict__ ent) {
    __shared__ float sums[128];
    const int w    = threadIdx.x >> 5;   // 8 warps
    const int lane = threadIdx.x & 31;

#pragma unroll
    for (int j = 0; j < 16; j++) {
        const int p = w + 8 * j;
        const float* src = g_part + (size_t)p * P1_CCHUNKS;
        float acc = 0.f;
#pragma unroll
        for (int m = 0; m < P1_CCHUNKS / 32; m++)
            acc += src[lane + 32 * m];
#pragma unroll
        for (int off = 16; off > 0; off >>= 1)
            acc += __shfl_xor_sync(0xFFFFFFFFu, acc, off);
        if (lane == 0) sums[p] = acc;
    }
    __syncthreads();

    const int s = threadIdx.x;
    if (s >= S) return;

    // N[s] at p = (s&7)*8 + (s>>3); A[s] at p + 64
    const int pN = (s & 7) * 8 + (s >> 3);
    __shared__ float shN[S], shA[S];
    shN[s] = sums[pN];
    shA[s] = sums[pN + 64];
    __syncthreads();

    int k1, k2;
    if (s == 0) {
        const int b0 = (ent[0] >= ent[1]) ? 1 : 0;
        k1 = b0; k2 = b0;
    } else if (s == S - 1) {
        const int bL = (ent[S - 1] >= ent[S - 2]) ? (S - 2) : (S - 1);
        k1 = bL; k2 = bL;
    } else {
        const float e  = ent[s];
        const float ep = ent[s - 1];
        const float en = ent[s + 1];
        const bool ge_next = e >= en, ge_prev = e >= ep;
        const bool le_next = e <= en, le_prev = e <= ep;
        if (ge_next && ge_prev)      { k1 = s - 1; k2 = s + 1; }
        else if (le_next && ge_prev) { k1 = s - 1; k2 = s;     }
        else if (ge_next && le_prev) { k1 = s;     k2 = s + 1; }
        else                         { k1 = s;     k2 = s;     }
    }

    const float d1 = (k1 == s) ? shN[s] : ((k1 == s - 1) ? shA[s - 1] : shA[s]);
    const float d2 = (k2 == s) ? shN[s] : ((k2 == s - 1) ? shA[s - 1] : shA[s]);

    const float scale = rsqrtf((float)D);
    const float s1 = d1 * scale, s2 = d2 * scale;
    const float m  = fmaxf(s1, s2);
    float w1 = expf(s1 - m), w2 = expf(s2 - m);
    const float inv = 1.f / (w1 + w2);
    w1 *= inv; w2 *= inv;

    float cp = 0.f, cc = 0.f, cn = 0.f;
    if (k1 == s - 1) cp += w1; else if (k1 == s) cc += w1; else cn += w1;
    if (k2 == s - 1) cp += w2; else if (k2 == s) cc += w2; else cn += w2;

    g_coeff[s]       = cp;
    g_coeff[64 + s]  = cc;
    g_coeff[128 + s] = cn;
}

// Pass 3: out[s] = cp[s]*q[s-1] + cc[s]*q[s] + cn[s]*q[s+1].
// block = (col chunk, s-tile of 16 rows). 2 independent rolling-window
// chains per thread. cp[0]==0 and cn[63]==0, so clamped halo reads are
// multiplied by zero.
__global__ __launch_bounds__(P3_THREADS) void out_kernel(const float4* __restrict__ q4,
                                                         float4* __restrict__ o4) {
    __shared__ float scp[S], scc[S], scn[S];
    const int t = threadIdx.x;
    if (t < S) {
        scp[t] = g_coeff[t];
        scc[t] = g_coeff[64 + t];
        scn[t] = g_coeff[128 + t];
    }
    __syncthreads();

    const int st = blockIdx.y * P3_STILE;
    const int j0 = blockIdx.x * P3_COLS + t;
    const int j1 = j0 + P3_THREADS;

    const int rprev = (st > 0) ? (st - 1) : 0;
    float4 a0 = q4[(size_t)rprev * DQ + j0];
    float4 a1 = q4[(size_t)rprev * DQ + j1];
    float4 b0 = q4[(size_t)st * DQ + j0];
    float4 b1 = q4[(size_t)st * DQ + j1];

#pragma unroll
    for (int i = 0; i < P3_STILE; i++) {
        const int s = st + i;
        const int rnext = (s + 1 < S) ? (s + 1) : (S - 1);
        float4 c0 = q4[(size_t)rnext * DQ + j0];
        float4 c1 = q4[(size_t)rnext * DQ + j1];

        const float cp = scp[s], cc = scc[s], cn = scn[s];

        float4 o0, o1;
        o0.x = cp * a0.x + cc * b0.x + cn * c0.x;
        o0.y = cp * a0.y + cc * b0.y + cn * c0.y;
        o0.z = cp * a0.z + cc * b0.z + cn * c0.z;
        o0.w = cp * a0.w + cc * b0.w + cn * c0.w;
        o1.x = cp * a1.x + cc * b1.x + cn * c1.x;
        o1.y = cp * a1.y + cc * b1.y + cn * c1.y;
        o1.z = cp * a1.z + cc * b1.z + cn * c1.z;
        o1.w = cp * a1.w + cc * b1.w + cn * c1.w;

        o4[(size_t)s * DQ + j0] = o0;
        o4[(size_t)s * DQ + j1] = o1;

        a0 = b0; b0 = c0;
        a1 = b1; b1 = c1;
    }
}

extern "C" void kernel_launch(void* const* d_in, const int* in_sizes, int n_in,
                              void* d_out, int out_size) {
    const float4* q4  = (const float4*)d_in[0];
    const float*  ent = (const float*)d_in[1];
    float4*       o4  = (float4*)d_out;

    dots_kernel<<<dim3(P1_CCHUNKS, P1_SGROUPS), P1_THREADS>>>(q4);
    coeff_kernel<<<1, 256>>>(ent);
    out_kernel<<<dim3(P3_CCHUNKS, P3_SGROUPS), P3_THREADS>>>(q4, o4);
}

// round 3
// speedup vs baseline: 1.3803x; 1.0739x over previous
#include <cuda_runtime.h>

#define S 64
#define D 524288            // 512*32*32
#define DQ (D / 4)          // 131072 float4 columns per row

// ---- pass 1 tiling ----
#define P1_THREADS 256
#define P1_GCOLS   4                          // columns per thread
#define P1_CCHUNKS (DQ / (P1_THREADS * P1_GCOLS))   // 128
#define P1_SGROUPS 8

// ---- pass 3 tiling ----
#define P3_THREADS 256
#define P3_COLS    512
#define P3_CCHUNKS (DQ / P3_COLS)   // 256
#define P3_STILE   16
#define P3_SGROUPS (S / P3_STILE)   // 4

// scratch (no device allocations allowed)
// g_part[p * 128 + cx]; p = k*8+sg, k<8 -> N[sg*8+k], k>=8 -> A[sg*8+k-8]
__device__ float g_part[128 * P1_CCHUNKS];
__device__ float g_coeff[3 * S];            // [cp(64)][cc(64)][cn(64)]

__device__ __forceinline__ float dot4(float4 a, float4 b) {
    return a.x * b.x + a.y * b.y + a.z * b.z + a.w * b.w;
}

// Pass 1: block = (col chunk cx, s-group sg). Each thread owns 4 float4
// columns (stride 256 for coalescing); per column it front-batches 9 row
// loads (MLP=9) and accumulates 8 N + 8 A partials. Shuffle reduction is
// amortized over the 4 columns.
__global__ __launch_bounds__(P1_THREADS) void dots_kernel(const float4* __restrict__ q4) {
    const int sg   = blockIdx.y;
    const int s0   = sg * 8;
    const int base = blockIdx.x * (P1_THREADS * P1_GCOLS) + threadIdx.x;
    const int w    = threadIdx.x >> 5;
    const int lane = threadIdx.x & 31;

    float v[16];
#pragma unroll
    for (int k = 0; k < 16; k++) v[k] = 0.f;

#pragma unroll
    for (int g = 0; g < P1_GCOLS; g++) {
        const int col = base + g * P1_THREADS;
        float4 r[9];
#pragma unroll
        for (int k = 0; k < 9; k++) {
            int row = s0 + k;
            if (row > S - 1) row = S - 1;   // sg==7 halo; its A[63] is never read
            r[k] = q4[(size_t)row * DQ + col];
        }
#pragma unroll
        for (int k = 0; k < 8; k++) {
            v[k]     += dot4(r[k], r[k]);        // N[s0+k]
            v[k + 8] += dot4(r[k], r[k + 1]);    // A[s0+k]
        }
    }

    // warp shuffle reduce all 16 values (amortized over 4 columns)
#pragma unroll
    for (int k = 0; k < 16; k++) {
#pragma unroll
        for (int off = 16; off > 0; off >>= 1)
            v[k] += __shfl_xor_sync(0xFFFFFFFFu, v[k], off);
    }

    __shared__ float sh[16][8];
    if (lane == 0) {
#pragma unroll
        for (int k = 0; k < 16; k++) sh[k][w] = v[k];
    }
    __syncthreads();

    if (threadIdx.x < 16) {
        float sum = 0.f;
#pragma unroll
        for (int j = 0; j < 8; j++) sum += sh[threadIdx.x][j];
        g_part[(threadIdx.x * 8 + sg) * P1_CCHUNKS + blockIdx.x] = sum;
    }
}

// Pass 2 (tiny): coalesced warp-per-target reduction of the 128 partials,
// then entropy branch ladder + softmax-of-2 -> per-slice (cp, cc, cn).
__global__ void coeff_kernel(const float* __restrict__ ent) {
    __shared__ float sums[128];
    const int w    = threadIdx.x >> 5;   // 8 warps
    const int lane = threadIdx.x & 31;

#pragma unroll
    for (int j = 0; j < 16; j++) {
        const int p = w + 8 * j;
        const float* src = g_part + (size_t)p * P1_CCHUNKS;
        float acc = 0.f;
#pragma unroll
        for (int m = 0; m < P1_CCHUNKS / 32; m++)
            acc += src[lane + 32 * m];
#pragma unroll
        for (int off = 16; off > 0; off >>= 1)
            acc += __shfl_xor_sync(0xFFFFFFFFu, acc, off);
        if (lane == 0) sums[p] = acc;
    }
    __syncthreads();

    const int s = threadIdx.x;
    if (s >= S) return;

    // N[s] at p = (s&7)*8 + (s>>3); A[s] at p + 64
    const int pN = (s & 7) * 8 + (s >> 3);
    __shared__ float shN[S], shA[S];
    shN[s] = sums[pN];
    shA[s] = sums[pN + 64];
    __syncthreads();

    int k1, k2;
    if (s == 0) {
        const int b0 = (ent[0] >= ent[1]) ? 1 : 0;
        k1 = b0; k2 = b0;
    } else if (s == S - 1) {
        const int bL = (ent[S - 1] >= ent[S - 2]) ? (S - 2) : (S - 1);
        k1 = bL; k2 = bL;
    } else {
        const float e  = ent[s];
        const float ep = ent[s - 1];
        const float en = ent[s + 1];
        const bool ge_next = e >= en, ge_prev = e >= ep;
        const bool le_next = e <= en, le_prev = e <= ep;
        if (ge_next && ge_prev)      { k1 = s - 1; k2 = s + 1; }
        else if (le_next && ge_prev) { k1 = s - 1; k2 = s;     }
        else if (ge_next && le_prev) { k1 = s;     k2 = s + 1; }
        else                         { k1 = s;     k2 = s;     }
    }

    const float d1 = (k1 == s) ? shN[s] : ((k1 == s - 1) ? shA[s - 1] : shA[s]);
    const float d2 = (k2 == s) ? shN[s] : ((k2 == s - 1) ? shA[s - 1] : shA[s]);

    const float scale = rsqrtf((float)D);
    const float s1 = d1 * scale, s2 = d2 * scale;
    const float m  = fmaxf(s1, s2);
    float w1 = expf(s1 - m), w2 = expf(s2 - m);
    const float inv = 1.f / (w1 + w2);
    w1 *= inv; w2 *= inv;

    float cp = 0.f, cc = 0.f, cn = 0.f;
    if (k1 == s - 1) cp += w1; else if (k1 == s) cc += w1; else cn += w1;
    if (k2 == s - 1) cp += w2; else if (k2 == s) cc += w2; else cn += w2;

    g_coeff[s]       = cp;
    g_coeff[64 + s]  = cc;
    g_coeff[128 + s] = cn;
}

// Pass 3: out[s] = cp[s]*q[s-1] + cc[s]*q[s] + cn[s]*q[s+1].
// Column chunks are processed in REVERSE order: dots_kernel just streamed
// the whole 128MB input through the 126MB L2, so the tail of its stream is
// resident — reading it back first converts DRAM reads into L2 hits.
// Output uses streaming stores (evict-first) to avoid evicting input rows.
__global__ __launch_bounds__(P3_THREADS) void out_kernel(const float4* __restrict__ q4,
                                                         float4* __restrict__ o4) {
    __shared__ float scp[S], scc[S], scn[S];
    const int t = threadIdx.x;
    if (t < S) {
        scp[t] = g_coeff[t];
        scc[t] = g_coeff[64 + t];
        scn[t] = g_coeff[128 + t];
    }
    __syncthreads();

    const int cx = (P3_CCHUNKS - 1) - blockIdx.x;   // boomerang order
    const int st = blockIdx.y * P3_STILE;
    const int j0 = cx * P3_COLS + t;
    const int j1 = j0 + P3_THREADS;

    const int rprev = (st > 0) ? (st - 1) : 0;
    float4 a0 = q4[(size_t)rprev * DQ + j0];
    float4 a1 = q4[(size_t)rprev * DQ + j1];
    float4 b0 = q4[(size_t)st * DQ + j0];
    float4 b1 = q4[(size_t)st * DQ + j1];

#pragma unroll
    for (int i = 0; i < P3_STILE; i++) {
        const int s = st + i;
        const int rnext = (s + 1 < S) ? (s + 1) : (S - 1);
        float4 c0 = q4[(size_t)rnext * DQ + j0];
        float4 c1 = q4[(size_t)rnext * DQ + j1];

        const float cp = scp[s], cc = scc[s], cn = scn[s];

        float4 o0, o1;
        o0.x = cp * a0.x + cc * b0.x + cn * c0.x;
        o0.y = cp * a0.y + cc * b0.y + cn * c0.y;
        o0.z = cp * a0.z + cc * b0.z + cn * c0.z;
        o0.w = cp * a0.w + cc * b0.w + cn * c0.w;
        o1.x = cp * a1.x + cc * b1.x + cn * c1.x;
        o1.y = cp * a1.y + cc * b1.y + cn * c1.y;
        o1.z = cp * a1.z + cc * b1.z + cn * c1.z;
        o1.w = cp * a1.w + cc * b1.w + cn * c1.w;

        __stcs(&o4[(size_t)s * DQ + j0], o0);
        __stcs(&o4[(size_t)s * DQ + j1], o1);

        a0 = b0; b0 = c0;
        a1 = b1; b1 = c1;
    }
}

extern "C" void kernel_launch(void* const* d_in, const int* in_sizes, int n_in,
                              void* d_out, int out_size) {
    const float4* q4  = (const float4*)d_in[0];
    const float*  ent = (const float*)d_in[1];
    float4*       o4  = (float4*)d_out;

    dots_kernel<<<dim3(P1_CCHUNKS, P1_SGROUPS), P1_THREADS>>>(q4);
    coeff_kernel<<<1, 256>>>(ent);
    out_kernel<<<dim3(P3_CCHUNKS, P3_SGROUPS), P3_THREADS>>>(q4, o4);
}